// round 1
// baseline (speedup 1.0000x reference)
#include <cuda_runtime.h>

#define NN 10000   // nodes
#define NE 160000  // edges
#define NB 4096    // batch
#define DD 512
#define HH 256

// ---------------- scratch (device globals; no runtime alloc) ----------------
__device__ float g_xw1[NN * HH];
__device__ float g_h[NN * HH];
__device__ float g_xw2[NN * DD];
__device__ float g_gcn[NN * DD];
__device__ float g_t1[NB * HH];
__device__ float g_img[NB * DD];
__device__ float g_imgT[DD * NB];
__device__ float g_logits[(size_t)NB * NB];
__device__ float g_dinv[NN];
__device__ int   g_counts[NN];
__device__ int   g_offsets[NN];
__device__ int   g_cursor[NN];
__device__ int   g_srcs[NE];
__device__ float g_wts[NE];
__device__ float g_terms[NB];

// ---------------- graph preprocessing ----------------
__global__ void k_init() {
    int i = blockIdx.x * blockDim.x + threadIdx.x;
    if (i < NN) { g_counts[i] = 0; g_cursor[i] = 0; }
}

__global__ void k_count(const int* __restrict__ ei) {
    int e = blockIdx.x * blockDim.x + threadIdx.x;
    if (e < NE) atomicAdd(&g_counts[ei[NE + e]], 1);
}

__global__ void k_dinv() {
    int i = blockIdx.x * blockDim.x + threadIdx.x;
    if (i < NN) g_dinv[i] = rsqrtf(1.0f + (float)g_counts[i]);
}

// single-block exclusive scan of g_counts -> g_offsets (10000 elems)
__global__ void k_scan() {
    __shared__ int sh[1024];
    const int CH = 10;  // 1024*10 >= 10000
    int t = threadIdx.x;
    int base = t * CH;
    int loc[CH];
    int sum = 0;
#pragma unroll
    for (int j = 0; j < CH; j++) {
        int idx = base + j;
        int c = (idx < NN) ? g_counts[idx] : 0;
        loc[j] = c; sum += c;
    }
    sh[t] = sum;
    __syncthreads();
    for (int off = 1; off < 1024; off <<= 1) {
        int v = (t >= off) ? sh[t - off] : 0;
        __syncthreads();
        sh[t] += v;
        __syncthreads();
    }
    int run = sh[t] - sum;  // exclusive prefix
#pragma unroll
    for (int j = 0; j < CH; j++) {
        int idx = base + j;
        if (idx < NN) g_offsets[idx] = run;
        run += loc[j];
    }
}

__global__ void k_fill(const int* __restrict__ ei) {
    int e = blockIdx.x * blockDim.x + threadIdx.x;
    if (e < NE) {
        int s = ei[e], d = ei[NE + e];
        int pos = g_offsets[d] + atomicAdd(&g_cursor[d], 1);
        g_srcs[pos] = s;
        g_wts[pos] = g_dinv[s] * g_dinv[d];
    }
}

// ---------------- GCN aggregation (CSR gather per dst node) ----------------
template <int F, bool RELU>
__global__ void k_agg(const float* __restrict__ xw, const float* __restrict__ bias,
                      float* __restrict__ out) {
    int v = blockIdx.x;
    int f = threadIdx.x;
    float dv = g_dinv[v];
    float sw = dv * dv;
    int rs = g_offsets[v];
    int re = rs + g_counts[v];
    if (F == 256) {
        float acc = sw * xw[(size_t)v * F + f];
        for (int i = rs; i < re; i++)
            acc += g_wts[i] * xw[(size_t)g_srcs[i] * F + f];
        acc += bias[f];
        out[(size_t)v * F + f] = RELU ? fmaxf(acc, 0.f) : acc;
    } else {
        float acc0 = sw * xw[(size_t)v * F + f];
        float acc1 = sw * xw[(size_t)v * F + f + 256];
        for (int i = rs; i < re; i++) {
            int s = g_srcs[i];
            float w = g_wts[i];
            acc0 += w * xw[(size_t)s * F + f];
            acc1 += w * xw[(size_t)s * F + f + 256];
        }
        acc0 += bias[f];
        acc1 += bias[f + 256];
        out[(size_t)v * F + f]       = RELU ? fmaxf(acc0, 0.f) : acc0;
        out[(size_t)v * F + f + 256] = RELU ? fmaxf(acc1, 0.f) : acc1;
    }
}

// ---------------- fp32 SGEMM: C[M,N] = A[M,K] @ B[K,N] (+bias, +relu) -------
// BM=128, BN=128, BK=8, 256 threads, 8x8 microtile. N % 128 == 0, K % 8 == 0.
template <bool RELU, bool GATHER>
__global__ void sgemm(int M, int N, int K,
                      const float* __restrict__ A, const float* __restrict__ B,
                      float* __restrict__ C, const float* __restrict__ bias,
                      const int* __restrict__ rowIdx) {
    __shared__ float As[8][128];
    __shared__ float Bs[8][128];
    int tid = threadIdx.x;
    int block_row = blockIdx.y * 128;
    int block_col = blockIdx.x * 128;
    int tr = tid >> 4;       // 0..15
    int tc = tid & 15;       // 0..15

    float acc[8][8];
#pragma unroll
    for (int i = 0; i < 8; i++)
#pragma unroll
        for (int j = 0; j < 8; j++) acc[i][j] = 0.f;

    int a_row = tid >> 1;            // 0..127
    int a_col = (tid & 1) * 4;       // 0 or 4
    int b_row = tid >> 5;            // 0..7
    int b_col = (tid & 31) * 4;      // 0..124

    int ga_row = block_row + a_row;
    bool a_valid = (ga_row < M);
    int a_idx = 0;
    if (a_valid) a_idx = GATHER ? rowIdx[ga_row] : ga_row;
    const float* Aptr = A + (size_t)a_idx * K;

    for (int k0 = 0; k0 < K; k0 += 8) {
        float4 av = a_valid ? *(const float4*)(Aptr + k0 + a_col)
                            : make_float4(0.f, 0.f, 0.f, 0.f);
        As[a_col + 0][a_row] = av.x;
        As[a_col + 1][a_row] = av.y;
        As[a_col + 2][a_row] = av.z;
        As[a_col + 3][a_row] = av.w;
        float4 bv = *(const float4*)(B + (size_t)(k0 + b_row) * N + block_col + b_col);
        *(float4*)&Bs[b_row][b_col] = bv;
        __syncthreads();
#pragma unroll
        for (int k = 0; k < 8; k++) {
            float4 a0 = *(const float4*)&As[k][tr * 8];
            float4 a1 = *(const float4*)&As[k][tr * 8 + 4];
            float4 b0 = *(const float4*)&Bs[k][tc * 8];
            float4 b1 = *(const float4*)&Bs[k][tc * 8 + 4];
            float ar[8] = {a0.x, a0.y, a0.z, a0.w, a1.x, a1.y, a1.z, a1.w};
            float br[8] = {b0.x, b0.y, b0.z, b0.w, b1.x, b1.y, b1.z, b1.w};
#pragma unroll
            for (int i = 0; i < 8; i++)
#pragma unroll
                for (int j = 0; j < 8; j++) acc[i][j] += ar[i] * br[j];
        }
        __syncthreads();
    }

#pragma unroll
    for (int i = 0; i < 8; i++) {
        int r = block_row + tr * 8 + i;
        if (r >= M) continue;
#pragma unroll
        for (int j = 0; j < 8; j += 4) {
            int c = block_col + tc * 8 + j;
            float4 v;
            v.x = acc[i][j + 0];
            v.y = acc[i][j + 1];
            v.z = acc[i][j + 2];
            v.w = acc[i][j + 3];
            if (bias) {
                v.x += bias[c + 0]; v.y += bias[c + 1];
                v.z += bias[c + 2]; v.w += bias[c + 3];
            }
            if (RELU) {
                v.x = fmaxf(v.x, 0.f); v.y = fmaxf(v.y, 0.f);
                v.z = fmaxf(v.z, 0.f); v.w = fmaxf(v.w, 0.f);
            }
            *(float4*)&C[(size_t)r * N + c] = v;
        }
    }
}

// ---------------- img transpose: [4096,512] -> [512,4096] ----------------
__global__ void k_transpose() {
    __shared__ float tile[32][33];
    int bx = blockIdx.x * 32;  // col in img (headdim), 0..511
    int by = blockIdx.y * 32;  // row in img (batch),  0..4095
    tile[threadIdx.y][threadIdx.x] = g_img[(size_t)(by + threadIdx.y) * DD + bx + threadIdx.x];
    __syncthreads();
    g_imgT[(size_t)(bx + threadIdx.y) * NB + by + threadIdx.x] = tile[threadIdx.x][threadIdx.y];
}

// ---------------- per-row online logsumexp + diag term ----------------
__global__ void k_lse(const int* __restrict__ label) {
    int i = blockIdx.x;
    const float* row = g_logits + (size_t)i * NB;
    float m = -3.0e38f, s = 0.f;
    for (int j = threadIdx.x; j < NB; j += 256) {
        float v = row[j];
        if (v > m) { s = s * __expf(m - v) + 1.f; m = v; }
        else        s += __expf(v - m);
    }
    __shared__ float sm[256], ss[256];
    sm[threadIdx.x] = m;
    ss[threadIdx.x] = s;
    __syncthreads();
    for (int off = 128; off > 0; off >>= 1) {
        if (threadIdx.x < off) {
            float m1 = sm[threadIdx.x], s1 = ss[threadIdx.x];
            float m2 = sm[threadIdx.x + off], s2 = ss[threadIdx.x + off];
            float M = fmaxf(m1, m2);
            sm[threadIdx.x] = M;
            ss[threadIdx.x] = s1 * __expf(m1 - M) + s2 * __expf(m2 - M);
        }
        __syncthreads();
    }
    if (threadIdx.x == 0) {
        float lse = sm[0] + logf(ss[0]);
        float diag = row[i];
        g_terms[i] = -(float)label[i] * (diag - lse);
    }
}

__global__ void k_final(float* __restrict__ out) {
    __shared__ float sh[256];
    float s = 0.f;
    for (int j = threadIdx.x; j < NB; j += 256) s += g_terms[j];
    sh[threadIdx.x] = s;
    __syncthreads();
    for (int off = 128; off > 0; off >>= 1) {
        if (threadIdx.x < off) sh[threadIdx.x] += sh[threadIdx.x + off];
        __syncthreads();
    }
    // triplet term is exactly relu(0 + margin) = 1.0
    if (threadIdx.x == 0) out[0] = sh[0] / (float)NB + 1.0f;
}

// ---------------- launch ----------------
extern "C" void kernel_launch(void* const* d_in, const int* in_sizes, int n_in,
                              void* d_out, int out_size) {
    const float* image  = (const float*)d_in[0];
    const float* xnodes = (const float*)d_in[1];
    const int*   ei     = (const int*)d_in[2];
    const int*   label  = (const int*)d_in[3];
    const float* W_img1 = (const float*)d_in[4];
    const float* b_img1 = (const float*)d_in[5];
    const float* W_img2 = (const float*)d_in[6];
    const float* b_img2 = (const float*)d_in[7];
    const float* W_g1   = (const float*)d_in[8];
    const float* b_g1   = (const float*)d_in[9];
    const float* W_g2   = (const float*)d_in[10];
    const float* b_g2   = (const float*)d_in[11];

    float *p_xw1, *p_h, *p_xw2, *p_gcn, *p_t1, *p_img, *p_imgT, *p_logits;
    cudaGetSymbolAddress((void**)&p_xw1, g_xw1);
    cudaGetSymbolAddress((void**)&p_h, g_h);
    cudaGetSymbolAddress((void**)&p_xw2, g_xw2);
    cudaGetSymbolAddress((void**)&p_gcn, g_gcn);
    cudaGetSymbolAddress((void**)&p_t1, g_t1);
    cudaGetSymbolAddress((void**)&p_img, g_img);
    cudaGetSymbolAddress((void**)&p_imgT, g_imgT);
    cudaGetSymbolAddress((void**)&p_logits, g_logits);

    // graph preprocessing -> CSR + symmetric norm weights
    k_init<<<(NN + 255) / 256, 256>>>();
    k_count<<<(NE + 255) / 256, 256>>>(ei);
    k_dinv<<<(NN + 255) / 256, 256>>>();
    k_scan<<<1, 1024>>>();
    k_fill<<<(NE + 255) / 256, 256>>>(ei);

    // GCN layer 1: xw1 = x_nodes @ W_g1 ; h = relu(agg + b)
    {
        dim3 grid(HH / 128, (NN + 127) / 128);
        sgemm<false, false><<<grid, 256>>>(NN, HH, DD, xnodes, W_g1, p_xw1, nullptr, nullptr);
    }
    k_agg<256, true><<<NN, 256>>>(p_xw1, b_g1, p_h);

    // GCN layer 2: xw2 = h @ W_g2 ; gcn = agg + b
    {
        dim3 grid(DD / 128, (NN + 127) / 128);
        sgemm<false, false><<<grid, 256>>>(NN, DD, HH, p_h, W_g2, p_xw2, nullptr, nullptr);
    }
    k_agg<512, false><<<NN, 256>>>(p_xw2, b_g2, p_gcn);

    // image MLP: t1 = relu(image@W1+b1); img = relu(t1@W2+b2)
    {
        dim3 grid(HH / 128, NB / 128);
        sgemm<true, false><<<grid, 256>>>(NB, HH, DD, image, W_img1, p_t1, b_img1, nullptr);
    }
    {
        dim3 grid(DD / 128, NB / 128);
        sgemm<true, false><<<grid, 256>>>(NB, DD, HH, p_t1, W_img2, p_img, b_img2, nullptr);
    }

    // imgT = img^T
    {
        dim3 grid(DD / 32, NB / 32);
        k_transpose<<<grid, dim3(32, 32)>>>();
    }

    // logits = gcn[label] @ imgT   (A-row gather through label)
    {
        dim3 grid(NB / 128, NB / 128);
        sgemm<false, true><<<grid, 256>>>(NB, NB, DD, p_gcn, p_imgT, p_logits, nullptr, label);
    }

    // per-row lse + diag, then final scalar
    k_lse<<<NB, 256>>>(label);
    k_final<<<1, 256>>>((float*)d_out);
}

// round 2
// speedup vs baseline: 3.1149x; 3.1149x over previous
#include <cuda_runtime.h>
#include <cuda_bf16.h>
#include <cstdint>

#define NN 10000   // nodes
#define NE 160000  // edges
#define NB 4096    // batch
#define DD 512
#define HH 256

// ---------------- scratch (device globals; no runtime alloc) ----------------
__device__ __nv_bfloat16 g_xa[NN * DD];       // x_nodes bf16
__device__ __nv_bfloat16 g_ia[NB * DD];       // image bf16
__device__ __nv_bfloat16 g_wg1t[HH * DD];     // W_g1^T bf16 [N][K]
__device__ __nv_bfloat16 g_wg2t[DD * HH];
__device__ __nv_bfloat16 g_wi1t[HH * DD];
__device__ __nv_bfloat16 g_wi2t[DD * HH];
__device__ float g_xw1[NN * HH];
__device__ __nv_bfloat16 g_h[NN * HH];
__device__ float g_xw2[NN * DD];
__device__ __nv_bfloat16 g_gcn[NN * DD];
__device__ __nv_bfloat16 g_t1[NB * HH];
__device__ __nv_bfloat16 g_img[NB * DD];
__device__ float g_logits[(size_t)NB * NB];
__device__ float g_dinv[NN];
__device__ int   g_counts[NN];
__device__ int   g_offsets[NN];
__device__ int   g_cursor[NN];
__device__ int   g_srcs[NE];
__device__ float g_wts[NE];
__device__ float g_terms[NB];

// ---------------- graph preprocessing ----------------
__global__ void k_init() {
    int i = blockIdx.x * blockDim.x + threadIdx.x;
    if (i < NN) { g_counts[i] = 0; g_cursor[i] = 0; }
}

__global__ void k_count(const int* __restrict__ ei) {
    int e = blockIdx.x * blockDim.x + threadIdx.x;
    if (e < NE) atomicAdd(&g_counts[ei[NE + e]], 1);
}

// scan + dinv fused (single block)
__global__ void k_scan() {
    __shared__ int sh[1024];
    const int CH = 10;
    int t = threadIdx.x;
    int base = t * CH;
    int loc[CH];
    int sum = 0;
#pragma unroll
    for (int j = 0; j < CH; j++) {
        int idx = base + j;
        int c = (idx < NN) ? g_counts[idx] : 0;
        loc[j] = c; sum += c;
        if (idx < NN) g_dinv[idx] = rsqrtf(1.0f + (float)c);
    }
    sh[t] = sum;
    __syncthreads();
    for (int off = 1; off < 1024; off <<= 1) {
        int v = (t >= off) ? sh[t - off] : 0;
        __syncthreads();
        sh[t] += v;
        __syncthreads();
    }
    int run = sh[t] - sum;
#pragma unroll
    for (int j = 0; j < CH; j++) {
        int idx = base + j;
        if (idx < NN) g_offsets[idx] = run;
        run += loc[j];
    }
}

__global__ void k_fill(const int* __restrict__ ei) {
    int e = blockIdx.x * blockDim.x + threadIdx.x;
    if (e < NE) {
        int s = ei[e], d = ei[NE + e];
        int pos = g_offsets[d] + atomicAdd(&g_cursor[d], 1);
        g_srcs[pos] = s;
        g_wts[pos] = g_dinv[s] * g_dinv[d];
    }
}

// ---------------- fp32 -> bf16 converters ----------------
__global__ void k_conv(const float* __restrict__ in, __nv_bfloat16* __restrict__ out, int n) {
    int i = blockIdx.x * blockDim.x + threadIdx.x;
    int i4 = i * 4;
    if (i4 + 3 < n) {
        float4 v = *(const float4*)(in + i4);
        out[i4 + 0] = __float2bfloat16_rn(v.x);
        out[i4 + 1] = __float2bfloat16_rn(v.y);
        out[i4 + 2] = __float2bfloat16_rn(v.z);
        out[i4 + 3] = __float2bfloat16_rn(v.w);
    } else {
        for (int j = i4; j < n; j++) out[j] = __float2bfloat16_rn(in[j]);
    }
}

// W [K][N] fp32 -> Wt [N][K] bf16
__global__ void k_convT(const float* __restrict__ W, __nv_bfloat16* __restrict__ Wt,
                        int K, int N) {
    __shared__ float tile[32][33];
    int k0 = blockIdx.y * 32, n0 = blockIdx.x * 32;
    tile[threadIdx.y][threadIdx.x] = W[(size_t)(k0 + threadIdx.y) * N + n0 + threadIdx.x];
    __syncthreads();
    Wt[(size_t)(n0 + threadIdx.y) * K + k0 + threadIdx.x] =
        __float2bfloat16_rn(tile[threadIdx.x][threadIdx.y]);
}

// ---------------- GCN aggregation (CSR gather), bf16 out ----------------
template <int F, bool RELU>
__global__ void k_agg(const float* __restrict__ xw, const float* __restrict__ bias,
                      __nv_bfloat16* __restrict__ out) {
    int v = blockIdx.x;
    int f = threadIdx.x;
    float dv = g_dinv[v];
    float sw = dv * dv;
    int rs = g_offsets[v];
    int re = rs + g_counts[v];
    if (F == 256) {
        float acc = sw * xw[(size_t)v * F + f];
        for (int i = rs; i < re; i++)
            acc += g_wts[i] * xw[(size_t)g_srcs[i] * F + f];
        acc += bias[f];
        out[(size_t)v * F + f] = __float2bfloat16_rn(RELU ? fmaxf(acc, 0.f) : acc);
    } else {
        float acc0 = sw * xw[(size_t)v * F + f];
        float acc1 = sw * xw[(size_t)v * F + f + 256];
        for (int i = rs; i < re; i++) {
            int s = g_srcs[i];
            float w = g_wts[i];
            acc0 += w * xw[(size_t)s * F + f];
            acc1 += w * xw[(size_t)s * F + f + 256];
        }
        acc0 += bias[f];
        acc1 += bias[f + 256];
        out[(size_t)v * F + f]       = __float2bfloat16_rn(RELU ? fmaxf(acc0, 0.f) : acc0);
        out[(size_t)v * F + f + 256] = __float2bfloat16_rn(RELU ? fmaxf(acc1, 0.f) : acc1);
    }
}

// ---------------- bf16 NT GEMM via mma.sync (HMMA), fp32 accum -------------
// C[M][N] = A[M][K] @ B[N][K]^T. BM=BN=128, BK=32, 256 threads (8 warps).
// Warp grid 2x4: each warp computes 64x32 via 4x4 m16n8k16 mmas.
// Requires: N % 128 == 0, K % 32 == 0, row byte strides 16B-aligned.
#define SSTR 40  // smem row stride in bf16 elems (padding kills bank conflicts)

template <bool RELU, bool BIAS, bool GATHER, bool OUT_BF16>
__global__ void bgemm(int M, int N, int K,
                      const __nv_bfloat16* __restrict__ A,
                      const __nv_bfloat16* __restrict__ B,
                      void* __restrict__ Cv,
                      const float* __restrict__ bias,
                      const int* __restrict__ rowIdx) {
    __shared__ __align__(16) __nv_bfloat16 As[128 * SSTR];
    __shared__ __align__(16) __nv_bfloat16 Bs[128 * SSTR];
    const int tid = threadIdx.x;
    const int lane = tid & 31, warp = tid >> 5;
    const int wm = (warp & 1) * 64, wn = (warp >> 1) * 32;
    const int g = lane >> 2, tg = lane & 3;
    const int brow = blockIdx.y * 128, bcol = blockIdx.x * 128;

    float acc[4][4][4];
#pragma unroll
    for (int a = 0; a < 4; a++)
#pragma unroll
        for (int b = 0; b < 4; b++)
#pragma unroll
            for (int c = 0; c < 4; c++) acc[a][b][c] = 0.f;

    const int lrow = tid >> 1;        // 0..127
    const int lk = (tid & 1) * 16;    // 0 or 16
    int arow = brow + lrow;
    bool aval = arow < M;
    long aidx = aval ? (GATHER ? (long)rowIdx[arow] : (long)arow) : 0;
    const __nv_bfloat16* Ap = A + aidx * K + lk;
    const __nv_bfloat16* Bp = B + (long)(bcol + lrow) * K + lk;

    for (int k0 = 0; k0 < K; k0 += 32) {
        uint4 av0, av1;
        if (aval) {
            av0 = *(const uint4*)(Ap + k0);
            av1 = *(const uint4*)(Ap + k0 + 8);
        } else {
            av0 = make_uint4(0, 0, 0, 0);
            av1 = make_uint4(0, 0, 0, 0);
        }
        *(uint4*)&As[lrow * SSTR + lk]     = av0;
        *(uint4*)&As[lrow * SSTR + lk + 8] = av1;
        *(uint4*)&Bs[lrow * SSTR + lk]     = *(const uint4*)(Bp + k0);
        *(uint4*)&Bs[lrow * SSTR + lk + 8] = *(const uint4*)(Bp + k0 + 8);
        __syncthreads();
#pragma unroll
        for (int kk = 0; kk < 32; kk += 16) {
            uint32_t af[4][4], bf[4][2];
#pragma unroll
            for (int mi = 0; mi < 4; mi++) {
                const __nv_bfloat16* p = &As[(wm + mi * 16 + g) * SSTR + kk + tg * 2];
                af[mi][0] = *(const uint32_t*)p;
                af[mi][1] = *(const uint32_t*)(p + 8 * SSTR);
                af[mi][2] = *(const uint32_t*)(p + 8);
                af[mi][3] = *(const uint32_t*)(p + 8 * SSTR + 8);
            }
#pragma unroll
            for (int ni = 0; ni < 4; ni++) {
                const __nv_bfloat16* p = &Bs[(wn + ni * 8 + g) * SSTR + kk + tg * 2];
                bf[ni][0] = *(const uint32_t*)p;
                bf[ni][1] = *(const uint32_t*)(p + 8);
            }
#pragma unroll
            for (int mi = 0; mi < 4; mi++)
#pragma unroll
                for (int ni = 0; ni < 4; ni++) {
                    asm volatile(
                        "mma.sync.aligned.m16n8k16.row.col.f32.bf16.bf16.f32 "
                        "{%0,%1,%2,%3}, {%4,%5,%6,%7}, {%8,%9}, {%0,%1,%2,%3};"
                        : "+f"(acc[mi][ni][0]), "+f"(acc[mi][ni][1]),
                          "+f"(acc[mi][ni][2]), "+f"(acc[mi][ni][3])
                        : "r"(af[mi][0]), "r"(af[mi][1]), "r"(af[mi][2]), "r"(af[mi][3]),
                          "r"(bf[ni][0]), "r"(bf[ni][1]));
                }
        }
        __syncthreads();
    }

#pragma unroll
    for (int mi = 0; mi < 4; mi++) {
#pragma unroll
        for (int half = 0; half < 2; half++) {
            int r = brow + wm + mi * 16 + g + half * 8;
            if (r >= M) continue;
#pragma unroll
            for (int ni = 0; ni < 4; ni++) {
                int c = bcol + wn + ni * 8 + tg * 2;
                float v0 = acc[mi][ni][half * 2 + 0];
                float v1 = acc[mi][ni][half * 2 + 1];
                if (BIAS) { v0 += bias[c]; v1 += bias[c + 1]; }
                if (RELU) { v0 = fmaxf(v0, 0.f); v1 = fmaxf(v1, 0.f); }
                if (OUT_BF16) {
                    __nv_bfloat162 h;
                    h.x = __float2bfloat16_rn(v0);
                    h.y = __float2bfloat16_rn(v1);
                    *(__nv_bfloat162*)((__nv_bfloat16*)Cv + (size_t)r * N + c) = h;
                } else {
                    *(float2*)((float*)Cv + (size_t)r * N + c) = make_float2(v0, v1);
                }
            }
        }
    }
}

// ---------------- per-row online logsumexp + diag term ----------------
__global__ void k_lse(const int* __restrict__ label) {
    int i = blockIdx.x;
    const float* row = g_logits + (size_t)i * NB;
    float m = -3.0e38f, s = 0.f;
    for (int j = threadIdx.x; j < NB; j += 256) {
        float v = row[j];
        if (v > m) { s = s * __expf(m - v) + 1.f; m = v; }
        else        s += __expf(v - m);
    }
    __shared__ float sm[256], ss[256];
    sm[threadIdx.x] = m;
    ss[threadIdx.x] = s;
    __syncthreads();
    for (int off = 128; off > 0; off >>= 1) {
        if (threadIdx.x < off) {
            float m1 = sm[threadIdx.x], s1 = ss[threadIdx.x];
            float m2 = sm[threadIdx.x + off], s2 = ss[threadIdx.x + off];
            float M = fmaxf(m1, m2);
            sm[threadIdx.x] = M;
            ss[threadIdx.x] = s1 * __expf(m1 - M) + s2 * __expf(m2 - M);
        }
        __syncthreads();
    }
    if (threadIdx.x == 0) {
        float lse = sm[0] + logf(ss[0]);
        float diag = row[i];
        g_terms[i] = -(float)label[i] * (diag - lse);
    }
}

__global__ void k_final(float* __restrict__ out) {
    __shared__ float sh[256];
    float s = 0.f;
    for (int j = threadIdx.x; j < NB; j += 256) s += g_terms[j];
    sh[threadIdx.x] = s;
    __syncthreads();
    for (int off = 128; off > 0; off >>= 1) {
        if (threadIdx.x < off) sh[threadIdx.x] += sh[threadIdx.x + off];
        __syncthreads();
    }
    if (threadIdx.x == 0) out[0] = sh[0] / (float)NB + 1.0f;  // + triplet (==1 exactly)
}

// ---------------- launch ----------------
extern "C" void kernel_launch(void* const* d_in, const int* in_sizes, int n_in,
                              void* d_out, int out_size) {
    const float* image  = (const float*)d_in[0];
    const float* xnodes = (const float*)d_in[1];
    const int*   ei     = (const int*)d_in[2];
    const int*   label  = (const int*)d_in[3];
    const float* W_img1 = (const float*)d_in[4];
    const float* b_img1 = (const float*)d_in[5];
    const float* W_img2 = (const float*)d_in[6];
    const float* b_img2 = (const float*)d_in[7];
    const float* W_g1   = (const float*)d_in[8];
    const float* b_g1   = (const float*)d_in[9];
    const float* W_g2   = (const float*)d_in[10];
    const float* b_g2   = (const float*)d_in[11];

    __nv_bfloat16 *p_xa, *p_ia, *p_wg1t, *p_wg2t, *p_wi1t, *p_wi2t, *p_h, *p_gcn, *p_t1, *p_img;
    float *p_xw1, *p_xw2, *p_logits;
    cudaGetSymbolAddress((void**)&p_xa, g_xa);
    cudaGetSymbolAddress((void**)&p_ia, g_ia);
    cudaGetSymbolAddress((void**)&p_wg1t, g_wg1t);
    cudaGetSymbolAddress((void**)&p_wg2t, g_wg2t);
    cudaGetSymbolAddress((void**)&p_wi1t, g_wi1t);
    cudaGetSymbolAddress((void**)&p_wi2t, g_wi2t);
    cudaGetSymbolAddress((void**)&p_h, g_h);
    cudaGetSymbolAddress((void**)&p_gcn, g_gcn);
    cudaGetSymbolAddress((void**)&p_t1, g_t1);
    cudaGetSymbolAddress((void**)&p_img, g_img);
    cudaGetSymbolAddress((void**)&p_xw1, g_xw1);
    cudaGetSymbolAddress((void**)&p_xw2, g_xw2);
    cudaGetSymbolAddress((void**)&p_logits, g_logits);

    // graph preprocessing -> CSR + symmetric norm weights
    k_init<<<(NN + 255) / 256, 256>>>();
    k_count<<<(NE + 255) / 256, 256>>>(ei);
    k_scan<<<1, 1024>>>();
    k_fill<<<(NE + 255) / 256, 256>>>(ei);

    // dtype conversions
    k_conv<<<(NN * DD / 4 + 255) / 256, 256>>>(xnodes, p_xa, NN * DD);
    k_conv<<<(NB * DD / 4 + 255) / 256, 256>>>(image, p_ia, NB * DD);
    k_convT<<<dim3(HH / 32, DD / 32), dim3(32, 32)>>>(W_g1, p_wg1t, DD, HH);
    k_convT<<<dim3(DD / 32, HH / 32), dim3(32, 32)>>>(W_g2, p_wg2t, HH, DD);
    k_convT<<<dim3(HH / 32, DD / 32), dim3(32, 32)>>>(W_img1, p_wi1t, DD, HH);
    k_convT<<<dim3(DD / 32, HH / 32), dim3(32, 32)>>>(W_img2, p_wi2t, HH, DD);

    // GCN layer 1: xw1 = xa @ Wg1 (fp32 out); h = bf16(relu(agg + b))
    {
        dim3 grid(HH / 128, (NN + 127) / 128);
        bgemm<false, false, false, false><<<grid, 256>>>(NN, HH, DD, p_xa, p_wg1t, p_xw1, nullptr, nullptr);
    }
    k_agg<256, true><<<NN, 256>>>(p_xw1, b_g1, p_h);

    // GCN layer 2: xw2 = h @ Wg2 (fp32 out); gcn = bf16(agg + b)
    {
        dim3 grid(DD / 128, (NN + 127) / 128);
        bgemm<false, false, false, false><<<grid, 256>>>(NN, DD, HH, p_h, p_wg2t, p_xw2, nullptr, nullptr);
    }
    k_agg<512, false><<<NN, 256>>>(p_xw2, b_g2, p_gcn);

    // image MLP: t1 = relu(ia@Wi1+b1) bf16; img = relu(t1@Wi2+b2) bf16
    {
        dim3 grid(HH / 128, NB / 128);
        bgemm<true, true, false, true><<<grid, 256>>>(NB, HH, DD, p_ia, p_wi1t, p_t1, b_img1, nullptr);
    }
    {
        dim3 grid(DD / 128, NB / 128);
        bgemm<true, true, false, true><<<grid, 256>>>(NB, DD, HH, p_t1, p_wi2t, p_img, b_img2, nullptr);
    }

    // logits = gcn[label] @ img^T  (NT: both operands are [*, K=512] bf16)
    {
        dim3 grid(NB / 128, NB / 128);
        bgemm<false, false, true, false><<<grid, 256>>>(NB, NB, DD, p_gcn, p_img, p_logits, nullptr, label);
    }

    // per-row lse + diag, then final scalar
    k_lse<<<NB, 256>>>(label);
    k_final<<<1, 256>>>((float*)d_out);
}

// round 3
// speedup vs baseline: 3.7868x; 1.2157x over previous
#include <cuda_runtime.h>
#include <cuda_bf16.h>
#include <cstdint>

#define NN 10000   // nodes
#define NE 160000  // edges
#define NB 4096    // batch
#define DD 512
#define HH 256
#define NCHUNK 8   // column chunks for fused logits+lse

// ---------------- scratch (device globals; no runtime alloc) ----------------
__device__ __nv_bfloat16 g_xa[NN * DD];
__device__ __nv_bfloat16 g_ia[NB * DD];
__device__ __nv_bfloat16 g_wg1t[HH * DD];
__device__ __nv_bfloat16 g_wg2t[DD * HH];
__device__ __nv_bfloat16 g_wi1t[HH * DD];
__device__ __nv_bfloat16 g_wi2t[DD * HH];
__device__ __nv_bfloat16 g_xw1[NN * HH];
__device__ __nv_bfloat16 g_h[NN * HH];
__device__ __nv_bfloat16 g_xw2[NN * DD];
__device__ __nv_bfloat16 g_gcn[NN * DD];
__device__ __nv_bfloat16 g_t1[NB * HH];
__device__ __nv_bfloat16 g_img[NB * DD];
__device__ float g_pm[NCHUNK * NB];
__device__ float g_ps[NCHUNK * NB];
__device__ float g_diag[NB];
__device__ float g_dinv[NN];
__device__ int   g_counts[NN];
__device__ int   g_offsets[NN];
__device__ int   g_cursor[NN];
__device__ int   g_srcs[NE];
__device__ float g_wts[NE];
__device__ float g_terms[NB];

// ---------------- graph preprocessing ----------------
__global__ void k_init() {
    int i = blockIdx.x * blockDim.x + threadIdx.x;
    if (i < NN) { g_counts[i] = 0; g_cursor[i] = 0; }
}

__global__ void k_count(const int* __restrict__ ei) {
    int e = blockIdx.x * blockDim.x + threadIdx.x;
    if (e < NE) atomicAdd(&g_counts[ei[NE + e]], 1);
}

__global__ void k_scan() {
    __shared__ int sh[1024];
    const int CH = 10;
    int t = threadIdx.x;
    int base = t * CH;
    int loc[CH];
    int sum = 0;
#pragma unroll
    for (int j = 0; j < CH; j++) {
        int idx = base + j;
        int c = (idx < NN) ? g_counts[idx] : 0;
        loc[j] = c; sum += c;
        if (idx < NN) g_dinv[idx] = rsqrtf(1.0f + (float)c);
    }
    sh[t] = sum;
    __syncthreads();
    for (int off = 1; off < 1024; off <<= 1) {
        int v = (t >= off) ? sh[t - off] : 0;
        __syncthreads();
        sh[t] += v;
        __syncthreads();
    }
    int run = sh[t] - sum;
#pragma unroll
    for (int j = 0; j < CH; j++) {
        int idx = base + j;
        if (idx < NN) g_offsets[idx] = run;
        run += loc[j];
    }
}

__global__ void k_fill(const int* __restrict__ ei) {
    int e = blockIdx.x * blockDim.x + threadIdx.x;
    if (e < NE) {
        int s = ei[e], d = ei[NE + e];
        int pos = g_offsets[d] + atomicAdd(&g_cursor[d], 1);
        g_srcs[pos] = s;
        g_wts[pos] = g_dinv[s] * g_dinv[d];
    }
}

// ---------------- fp32 -> bf16 converters ----------------
__global__ void k_conv(const float* __restrict__ in, __nv_bfloat16* __restrict__ out, int n) {
    int i4 = (blockIdx.x * blockDim.x + threadIdx.x) * 4;
    if (i4 + 3 < n) {
        float4 v = *(const float4*)(in + i4);
        out[i4 + 0] = __float2bfloat16_rn(v.x);
        out[i4 + 1] = __float2bfloat16_rn(v.y);
        out[i4 + 2] = __float2bfloat16_rn(v.z);
        out[i4 + 3] = __float2bfloat16_rn(v.w);
    } else {
        for (int j = i4; j < n; j++) out[j] = __float2bfloat16_rn(in[j]);
    }
}

__global__ void k_convT(const float* __restrict__ W, __nv_bfloat16* __restrict__ Wt,
                        int K, int N) {
    __shared__ float tile[32][33];
    int k0 = blockIdx.y * 32, n0 = blockIdx.x * 32;
    tile[threadIdx.y][threadIdx.x] = W[(size_t)(k0 + threadIdx.y) * N + n0 + threadIdx.x];
    __syncthreads();
    Wt[(size_t)(n0 + threadIdx.y) * K + k0 + threadIdx.x] =
        __float2bfloat16_rn(tile[threadIdx.x][threadIdx.y]);
}

// ---------------- GCN aggregation (CSR gather), bf16 in/out ----------------
template <bool RELU>
__global__ void k_agg256(const __nv_bfloat16* __restrict__ xw, const float* __restrict__ bias,
                         __nv_bfloat16* __restrict__ out) {
    int v = blockIdx.x;
    int f = threadIdx.x;  // 256
    float dv = g_dinv[v];
    float sw = dv * dv;
    int rs = g_offsets[v];
    int re = rs + g_counts[v];
    float acc = sw * __bfloat162float(xw[(size_t)v * 256 + f]);
    for (int i = rs; i < re; i++)
        acc += g_wts[i] * __bfloat162float(xw[(size_t)g_srcs[i] * 256 + f]);
    acc += bias[f];
    out[(size_t)v * 256 + f] = __float2bfloat16_rn(RELU ? fmaxf(acc, 0.f) : acc);
}

template <bool RELU>
__global__ void k_agg512(const __nv_bfloat16* __restrict__ xw, const float* __restrict__ bias,
                         __nv_bfloat16* __restrict__ out) {
    int v = blockIdx.x;
    int f2 = threadIdx.x * 2;  // 256 threads, 2 cols each via bf16x2
    float dv = g_dinv[v];
    float sw = dv * dv;
    int rs = g_offsets[v];
    int re = rs + g_counts[v];
    float2 self = __bfloat1622float2(*(const __nv_bfloat162*)(xw + (size_t)v * 512 + f2));
    float a0 = sw * self.x, a1 = sw * self.y;
    for (int i = rs; i < re; i++) {
        float w = g_wts[i];
        float2 m = __bfloat1622float2(*(const __nv_bfloat162*)(xw + (size_t)g_srcs[i] * 512 + f2));
        a0 += w * m.x;
        a1 += w * m.y;
    }
    a0 += bias[f2]; a1 += bias[f2 + 1];
    if (RELU) { a0 = fmaxf(a0, 0.f); a1 = fmaxf(a1, 0.f); }
    __nv_bfloat162 h;
    h.x = __float2bfloat16_rn(a0);
    h.y = __float2bfloat16_rn(a1);
    *(__nv_bfloat162*)(out + (size_t)v * 512 + f2) = h;
}

// ---------------- cp.async helpers ----------------
__device__ __forceinline__ void cp16(uint32_t smem, const void* gmem, int srcBytes) {
    asm volatile("cp.async.cg.shared.global [%0], [%1], 16, %2;"
                 :: "r"(smem), "l"(gmem), "r"(srcBytes));
}
__device__ __forceinline__ void cp_commit() { asm volatile("cp.async.commit_group;"); }
__device__ __forceinline__ void cp_wait1() { asm volatile("cp.async.wait_group 1;"); }
__device__ __forceinline__ void cp_wait0() { asm volatile("cp.async.wait_group 0;"); }

#define SSTR 40  // smem row stride in bf16 elems

// warp-tile mma: computes 64x32 (per warp) from one 128x32 As/Bs stage
__device__ __forceinline__ void mma_tile(const __nv_bfloat16* As_, const __nv_bfloat16* Bs_,
                                         int wm, int wn, int g, int tg,
                                         float acc[4][4][4]) {
#pragma unroll
    for (int kk = 0; kk < 32; kk += 16) {
        uint32_t af[4][4], bf[4][2];
#pragma unroll
        for (int mi = 0; mi < 4; mi++) {
            const __nv_bfloat16* p = &As_[(wm + mi * 16 + g) * SSTR + kk + tg * 2];
            af[mi][0] = *(const uint32_t*)p;
            af[mi][1] = *(const uint32_t*)(p + 8 * SSTR);
            af[mi][2] = *(const uint32_t*)(p + 8);
            af[mi][3] = *(const uint32_t*)(p + 8 * SSTR + 8);
        }
#pragma unroll
        for (int ni = 0; ni < 4; ni++) {
            const __nv_bfloat16* p = &Bs_[(wn + ni * 8 + g) * SSTR + kk + tg * 2];
            bf[ni][0] = *(const uint32_t*)p;
            bf[ni][1] = *(const uint32_t*)(p + 8);
        }
#pragma unroll
        for (int mi = 0; mi < 4; mi++)
#pragma unroll
            for (int ni = 0; ni < 4; ni++) {
                asm volatile(
                    "mma.sync.aligned.m16n8k16.row.col.f32.bf16.bf16.f32 "
                    "{%0,%1,%2,%3}, {%4,%5,%6,%7}, {%8,%9}, {%0,%1,%2,%3};"
                    : "+f"(acc[mi][ni][0]), "+f"(acc[mi][ni][1]),
                      "+f"(acc[mi][ni][2]), "+f"(acc[mi][ni][3])
                    : "r"(af[mi][0]), "r"(af[mi][1]), "r"(af[mi][2]), "r"(af[mi][3]),
                      "r"(bf[ni][0]), "r"(bf[ni][1]));
            }
    }
}

// ---------------- bf16 NT GEMM, 2-stage cp.async pipeline --------------
// C[M][N] = A[M][K] @ B[N][K]^T. BM=BN=128, BK=32, 256 threads.
template <bool RELU, bool BIAS>
__global__ void bgemm(int M, int N, int K,
                      const __nv_bfloat16* __restrict__ A,
                      const __nv_bfloat16* __restrict__ B,
                      __nv_bfloat16* __restrict__ C,
                      const float* __restrict__ bias) {
    __shared__ __align__(16) __nv_bfloat16 As[2][128 * SSTR];
    __shared__ __align__(16) __nv_bfloat16 Bs[2][128 * SSTR];
    const int tid = threadIdx.x;
    const int lane = tid & 31, warp = tid >> 5;
    const int wm = (warp & 1) * 64, wn = (warp >> 1) * 32;
    const int g = lane >> 2, tg = lane & 3;
    const int brow = blockIdx.y * 128, bcol = blockIdx.x * 128;

    float acc[4][4][4];
#pragma unroll
    for (int a = 0; a < 4; a++)
#pragma unroll
        for (int b = 0; b < 4; b++)
#pragma unroll
            for (int c = 0; c < 4; c++) acc[a][b][c] = 0.f;

    const int lrow = tid >> 1;
    const int lk = (tid & 1) * 16;
    int arow = brow + lrow;
    bool aval = arow < M;
    int aSrc = aval ? 16 : 0;
    const __nv_bfloat16* Ap = A + (long)(aval ? arow : 0) * K + lk;
    const __nv_bfloat16* Bp = B + (long)(bcol + lrow) * K + lk;

    uint32_t sA = (uint32_t)__cvta_generic_to_shared(&As[0][0]) + (lrow * SSTR + lk) * 2;
    uint32_t sB = (uint32_t)__cvta_generic_to_shared(&Bs[0][0]) + (lrow * SSTR + lk) * 2;
    const uint32_t STG = 128 * SSTR * 2;

    const int nK = K / 32;
    // stage 0
    cp16(sA, Ap, aSrc); cp16(sA + 16, Ap + 8, aSrc);
    cp16(sB, Bp, 16);   cp16(sB + 16, Bp + 8, 16);
    cp_commit();

    for (int i = 0; i < nK; i++) {
        if (i + 1 < nK) {
            int k0 = (i + 1) * 32;
            uint32_t b = (i + 1) & 1;
            cp16(sA + b * STG, Ap + k0, aSrc); cp16(sA + b * STG + 16, Ap + k0 + 8, aSrc);
            cp16(sB + b * STG, Bp + k0, 16);   cp16(sB + b * STG + 16, Bp + k0 + 8, 16);
            cp_commit();
            cp_wait1();
        } else {
            cp_wait0();
        }
        __syncthreads();
        mma_tile(As[i & 1], Bs[i & 1], wm, wn, g, tg, acc);
        __syncthreads();
    }

#pragma unroll
    for (int mi = 0; mi < 4; mi++) {
#pragma unroll
        for (int half = 0; half < 2; half++) {
            int r = brow + wm + mi * 16 + g + half * 8;
            if (r >= M) continue;
#pragma unroll
            for (int ni = 0; ni < 4; ni++) {
                int c = bcol + wn + ni * 8 + tg * 2;
                float v0 = acc[mi][ni][half * 2 + 0];
                float v1 = acc[mi][ni][half * 2 + 1];
                if (BIAS) { v0 += bias[c]; v1 += bias[c + 1]; }
                if (RELU) { v0 = fmaxf(v0, 0.f); v1 = fmaxf(v1, 0.f); }
                __nv_bfloat162 h;
                h.x = __float2bfloat16_rn(v0);
                h.y = __float2bfloat16_rn(v1);
                *(__nv_bfloat162*)(C + (size_t)r * N + c) = h;
            }
        }
    }
}

// ------- fused logits GEMM + online row LSE + diag extraction -------------
// grid = (NCHUNK=8, NB/128=32). Each block: 128 rows x 512 cols (4 tiles of 128).
__global__ void k_logits_lse(const __nv_bfloat16* __restrict__ A,   // gcn [NN][DD]
                             const __nv_bfloat16* __restrict__ B,   // img [NB][DD]
                             const int* __restrict__ label) {
    __shared__ __align__(16) __nv_bfloat16 As[2][128 * SSTR];
    __shared__ __align__(16) __nv_bfloat16 Bs[2][128 * SSTR];
    __shared__ float red_m[4][128];
    __shared__ float red_s[4][128];
    __shared__ float run_m[128];
    __shared__ float run_s[128];

    const int tid = threadIdx.x;
    const int lane = tid & 31, warp = tid >> 5;
    const int wm = (warp & 1) * 64, wn = (warp >> 1) * 32;
    const int wnIdx = warp >> 1;
    const int g = lane >> 2, tg = lane & 3;
    const int brow = blockIdx.y * 128;
    const int chunk = blockIdx.x;

    const int lrow = tid >> 1;
    const int lk = (tid & 1) * 16;
    const __nv_bfloat16* Ap = A + (long)label[brow + lrow] * DD + lk;

    uint32_t sA = (uint32_t)__cvta_generic_to_shared(&As[0][0]) + (lrow * SSTR + lk) * 2;
    uint32_t sB = (uint32_t)__cvta_generic_to_shared(&Bs[0][0]) + (lrow * SSTR + lk) * 2;
    const uint32_t STG = 128 * SSTR * 2;

    if (tid < 128) { run_m[tid] = -3.0e38f; run_s[tid] = 0.f; }

    for (int nt = 0; nt < 4; nt++) {
        const int bcol = chunk * 512 + nt * 128;
        const __nv_bfloat16* Bp = B + (long)(bcol + lrow) * DD + lk;

        float acc[4][4][4];
#pragma unroll
        for (int a = 0; a < 4; a++)
#pragma unroll
            for (int b = 0; b < 4; b++)
#pragma unroll
                for (int c = 0; c < 4; c++) acc[a][b][c] = 0.f;

        const int nK = DD / 32;
        cp16(sA, Ap, 16); cp16(sA + 16, Ap + 8, 16);
        cp16(sB, Bp, 16); cp16(sB + 16, Bp + 8, 16);
        cp_commit();
        for (int i = 0; i < nK; i++) {
            if (i + 1 < nK) {
                int k0 = (i + 1) * 32;
                uint32_t b = (i + 1) & 1;
                cp16(sA + b * STG, Ap + k0, 16); cp16(sA + b * STG + 16, Ap + k0 + 8, 16);
                cp16(sB + b * STG, Bp + k0, 16); cp16(sB + b * STG + 16, Bp + k0 + 8, 16);
                cp_commit();
                cp_wait1();
            } else {
                cp_wait0();
            }
            __syncthreads();
            mma_tile(As[i & 1], Bs[i & 1], wm, wn, g, tg, acc);
            __syncthreads();
        }

        // ---- epilogue: online LSE over this 128x128 tile ----
        // pass 1: per-row tile max
#pragma unroll
        for (int mi = 0; mi < 4; mi++) {
#pragma unroll
            for (int half = 0; half < 2; half++) {
                int row = wm + mi * 16 + g + half * 8;
                float v = -3.0e38f;
#pragma unroll
                for (int ni = 0; ni < 4; ni++)
                    v = fmaxf(v, fmaxf(acc[mi][ni][half * 2], acc[mi][ni][half * 2 + 1]));
                v = fmaxf(v, __shfl_xor_sync(0xffffffffu, v, 1));
                v = fmaxf(v, __shfl_xor_sync(0xffffffffu, v, 2));
                if (tg == 0) red_m[wnIdx][row] = v;
            }
        }
        __syncthreads();
        if (tid < 128) {
            float tm = fmaxf(fmaxf(red_m[0][tid], red_m[1][tid]),
                             fmaxf(red_m[2][tid], red_m[3][tid]));
            float om = run_m[tid];
            float nm = fmaxf(om, tm);
            run_s[tid] *= __expf(om - nm);
            run_m[tid] = nm;
        }
        __syncthreads();
        // pass 2: sum of exp + diag
#pragma unroll
        for (int mi = 0; mi < 4; mi++) {
#pragma unroll
            for (int half = 0; half < 2; half++) {
                int row = wm + mi * 16 + g + half * 8;
                float nm = run_m[row];
                float ps = 0.f;
#pragma unroll
                for (int ni = 0; ni < 4; ni++) {
#pragma unroll
                    for (int j = 0; j < 2; j++) {
                        float v = acc[mi][ni][half * 2 + j];
                        ps += __expf(v - nm);
                        int gc = bcol + wn + ni * 8 + tg * 2 + j;
                        if (gc == brow + row) g_diag[brow + row] = v;
                    }
                }
                ps += __shfl_xor_sync(0xffffffffu, ps, 1);
                ps += __shfl_xor_sync(0xffffffffu, ps, 2);
                if (tg == 0) red_s[wnIdx][row] = ps;
            }
        }
        __syncthreads();
        if (tid < 128)
            run_s[tid] += red_s[0][tid] + red_s[1][tid] + red_s[2][tid] + red_s[3][tid];
        __syncthreads();
    }

    if (tid < 128) {
        g_pm[chunk * NB + brow + tid] = run_m[tid];
        g_ps[chunk * NB + brow + tid] = run_s[tid];
    }
}

// ---------------- merge chunk partials -> per-row term ----------------
__global__ void k_merge(const int* __restrict__ label) {
    int i = blockIdx.x * blockDim.x + threadIdx.x;
    if (i >= NB) return;
    float m = -3.0e38f;
#pragma unroll
    for (int c = 0; c < NCHUNK; c++) m = fmaxf(m, g_pm[c * NB + i]);
    float s = 0.f;
#pragma unroll
    for (int c = 0; c < NCHUNK; c++) s += g_ps[c * NB + i] * __expf(g_pm[c * NB + i] - m);
    float lse = m + logf(s);
    g_terms[i] = -(float)label[i] * (g_diag[i] - lse);
}

__global__ void k_final(float* __restrict__ out) {
    __shared__ float sh[256];
    float s = 0.f;
    for (int j = threadIdx.x; j < NB; j += 256) s += g_terms[j];
    sh[threadIdx.x] = s;
    __syncthreads();
    for (int off = 128; off > 0; off >>= 1) {
        if (threadIdx.x < off) sh[threadIdx.x] += sh[threadIdx.x + off];
        __syncthreads();
    }
    if (threadIdx.x == 0) out[0] = sh[0] / (float)NB + 1.0f;  // + triplet (==1 exactly)
}

// ---------------- launch ----------------
extern "C" void kernel_launch(void* const* d_in, const int* in_sizes, int n_in,
                              void* d_out, int out_size) {
    const float* image  = (const float*)d_in[0];
    const float* xnodes = (const float*)d_in[1];
    const int*   ei     = (const int*)d_in[2];
    const int*   label  = (const int*)d_in[3];
    const float* W_img1 = (const float*)d_in[4];
    const float* b_img1 = (const float*)d_in[5];
    const float* W_img2 = (const float*)d_in[6];
    const float* b_img2 = (const float*)d_in[7];
    const float* W_g1   = (const float*)d_in[8];
    const float* b_g1   = (const float*)d_in[9];
    const float* W_g2   = (const float*)d_in[10];
    const float* b_g2   = (const float*)d_in[11];

    __nv_bfloat16 *p_xa, *p_ia, *p_wg1t, *p_wg2t, *p_wi1t, *p_wi2t;
    __nv_bfloat16 *p_xw1, *p_h, *p_xw2, *p_gcn, *p_t1, *p_img;
    cudaGetSymbolAddress((void**)&p_xa, g_xa);
    cudaGetSymbolAddress((void**)&p_ia, g_ia);
    cudaGetSymbolAddress((void**)&p_wg1t, g_wg1t);
    cudaGetSymbolAddress((void**)&p_wg2t, g_wg2t);
    cudaGetSymbolAddress((void**)&p_wi1t, g_wi1t);
    cudaGetSymbolAddress((void**)&p_wi2t, g_wi2t);
    cudaGetSymbolAddress((void**)&p_xw1, g_xw1);
    cudaGetSymbolAddress((void**)&p_h, g_h);
    cudaGetSymbolAddress((void**)&p_xw2, g_xw2);
    cudaGetSymbolAddress((void**)&p_gcn, g_gcn);
    cudaGetSymbolAddress((void**)&p_t1, g_t1);
    cudaGetSymbolAddress((void**)&p_img, g_img);

    // graph preprocessing -> CSR + symmetric norm weights
    k_init<<<(NN + 255) / 256, 256>>>();
    k_count<<<(NE + 255) / 256, 256>>>(ei);
    k_scan<<<1, 1024>>>();
    k_fill<<<(NE + 255) / 256, 256>>>(ei);

    // dtype conversions
    k_conv<<<(NN * DD / 4 + 255) / 256, 256>>>(xnodes, p_xa, NN * DD);
    k_conv<<<(NB * DD / 4 + 255) / 256, 256>>>(image, p_ia, NB * DD);
    k_convT<<<dim3(HH / 32, DD / 32), dim3(32, 32)>>>(W_g1, p_wg1t, DD, HH);
    k_convT<<<dim3(DD / 32, HH / 32), dim3(32, 32)>>>(W_g2, p_wg2t, HH, DD);
    k_convT<<<dim3(HH / 32, DD / 32), dim3(32, 32)>>>(W_img1, p_wi1t, DD, HH);
    k_convT<<<dim3(DD / 32, HH / 32), dim3(32, 32)>>>(W_img2, p_wi2t, HH, DD);

    // GCN layer 1
    {
        dim3 grid(HH / 128, (NN + 127) / 128);
        bgemm<false, false><<<grid, 256>>>(NN, HH, DD, p_xa, p_wg1t, p_xw1, nullptr);
    }
    k_agg256<true><<<NN, 256>>>(p_xw1, b_g1, p_h);

    // GCN layer 2
    {
        dim3 grid(DD / 128, (NN + 127) / 128);
        bgemm<false, false><<<grid, 256>>>(NN, DD, HH, p_h, p_wg2t, p_xw2, nullptr);
    }
    k_agg512<false><<<NN, 256>>>(p_xw2, b_g2, p_gcn);

    // image MLP
    {
        dim3 grid(HH / 128, NB / 128);
        bgemm<true, true><<<grid, 256>>>(NB, HH, DD, p_ia, p_wi1t, p_t1, b_img1);
    }
    {
        dim3 grid(DD / 128, NB / 128);
        bgemm<true, true><<<grid, 256>>>(NB, DD, HH, p_t1, p_wi2t, p_img, b_img2);
    }

    // fused logits + row-wise LSE partials + diag
    {
        dim3 grid(NCHUNK, NB / 128);
        k_logits_lse<<<grid, 256>>>(p_gcn, p_img, label);
    }
    k_merge<<<(NB + 255) / 256, 256>>>(label);
    k_final<<<1, 256>>>((float*)d_out);
}

// round 4
// speedup vs baseline: 4.1178x; 1.0874x over previous
#include <cuda_runtime.h>
#include <cuda_bf16.h>
#include <cstdint>

#define NN 10000   // nodes
#define NE 160000  // edges
#define NB 4096    // batch
#define DD 512
#define HH 256
#define NCHUNK 8   // column chunks for fused logits+lse

// ---------------- scratch (device globals; no runtime alloc) ----------------
__device__ __nv_bfloat16 g_xa[NN * DD];
__device__ __nv_bfloat16 g_ia[NB * DD];
__device__ __nv_bfloat16 g_wg1t[HH * DD];
__device__ __nv_bfloat16 g_wg2t[DD * HH];
__device__ __nv_bfloat16 g_wi1t[HH * DD];
__device__ __nv_bfloat16 g_wi2t[DD * HH];
__device__ __nv_bfloat16 g_xw1[NN * HH];
__device__ __nv_bfloat16 g_h[NN * HH];
__device__ __nv_bfloat16 g_xw2[NN * DD];
__device__ __nv_bfloat16 g_gcn[NN * DD];
__device__ __nv_bfloat16 g_t1[NB * HH];
__device__ __nv_bfloat16 g_img[NB * DD];
__device__ float g_pm[NCHUNK * NB];
__device__ float g_ps[NCHUNK * NB];
__device__ float g_diag[NB];
__device__ float g_dinv[NN];
__device__ int   g_counts[NN];
__device__ int   g_offsets[NN];
__device__ int   g_cursor[NN];
__device__ int   g_srcs[NE];
__device__ float g_wts[NE];

// ---------------- graph preprocessing ----------------
__global__ void k_init() {
    int i = blockIdx.x * blockDim.x + threadIdx.x;
    if (i < NN) { g_counts[i] = 0; g_cursor[i] = 0; }
}

__global__ void k_count(const int* __restrict__ ei) {
    int e = blockIdx.x * blockDim.x + threadIdx.x;
    if (e < NE) atomicAdd(&g_counts[ei[NE + e]], 1);
}

// shuffle-based scan + dinv (single block, 1024 threads)
__global__ void k_scan() {
    __shared__ int wsum[32];
    const int CH = 10;
    int t = threadIdx.x;
    int lane = t & 31, warp = t >> 5;
    int base = t * CH;
    int loc[CH];
    int sum = 0;
#pragma unroll
    for (int j = 0; j < CH; j++) {
        int idx = base + j;
        int c = (idx < NN) ? g_counts[idx] : 0;
        loc[j] = c; sum += c;
        if (idx < NN) g_dinv[idx] = rsqrtf(1.0f + (float)c);
    }
    // warp inclusive scan
    int inc = sum;
#pragma unroll
    for (int off = 1; off < 32; off <<= 1) {
        int v = __shfl_up_sync(0xffffffffu, inc, off);
        if (lane >= off) inc += v;
    }
    if (lane == 31) wsum[warp] = inc;
    __syncthreads();
    if (warp == 0) {
        int v = wsum[lane];
        int wi = v;
#pragma unroll
        for (int off = 1; off < 32; off <<= 1) {
            int u = __shfl_up_sync(0xffffffffu, wi, off);
            if (lane >= off) wi += u;
        }
        wsum[lane] = wi - v;  // exclusive warp offset
    }
    __syncthreads();
    int run = wsum[warp] + (inc - sum);  // exclusive prefix for this thread
#pragma unroll
    for (int j = 0; j < CH; j++) {
        int idx = base + j;
        if (idx < NN) g_offsets[idx] = run;
        run += loc[j];
    }
}

__global__ void k_fill(const int* __restrict__ ei) {
    int e = blockIdx.x * blockDim.x + threadIdx.x;
    if (e < NE) {
        int s = ei[e], d = ei[NE + e];
        int pos = g_offsets[d] + atomicAdd(&g_cursor[d], 1);
        g_srcs[pos] = s;
        g_wts[pos] = g_dinv[s] * g_dinv[d];
    }
}

// ---------------- fp32 -> bf16 converters ----------------
__global__ void k_conv(const float* __restrict__ in, __nv_bfloat16* __restrict__ out, int n) {
    int i4 = (blockIdx.x * blockDim.x + threadIdx.x) * 4;
    if (i4 + 3 < n) {
        float4 v = *(const float4*)(in + i4);
        out[i4 + 0] = __float2bfloat16_rn(v.x);
        out[i4 + 1] = __float2bfloat16_rn(v.y);
        out[i4 + 2] = __float2bfloat16_rn(v.z);
        out[i4 + 3] = __float2bfloat16_rn(v.w);
    } else {
        for (int j = i4; j < n; j++) out[j] = __float2bfloat16_rn(in[j]);
    }
}

__global__ void k_convT(const float* __restrict__ W, __nv_bfloat16* __restrict__ Wt,
                        int K, int N) {
    __shared__ float tile[32][33];
    int k0 = blockIdx.y * 32, n0 = blockIdx.x * 32;
    tile[threadIdx.y][threadIdx.x] = W[(size_t)(k0 + threadIdx.y) * N + n0 + threadIdx.x];
    __syncthreads();
    Wt[(size_t)(n0 + threadIdx.y) * K + k0 + threadIdx.x] =
        __float2bfloat16_rn(tile[threadIdx.x][threadIdx.y]);
}

// ---------------- GCN aggregation (CSR gather), bf16 in/out ----------------
template <bool RELU>
__global__ void k_agg256(const __nv_bfloat16* __restrict__ xw, const float* __restrict__ bias,
                         __nv_bfloat16* __restrict__ out) {
    int v = blockIdx.x;
    int f = threadIdx.x;
    float dv = g_dinv[v];
    float sw = dv * dv;
    int rs = g_offsets[v];
    int re = rs + g_counts[v];
    float acc = sw * __bfloat162float(xw[(size_t)v * 256 + f]);
    for (int i = rs; i < re; i++)
        acc += g_wts[i] * __bfloat162float(xw[(size_t)g_srcs[i] * 256 + f]);
    acc += bias[f];
    out[(size_t)v * 256 + f] = __float2bfloat16_rn(RELU ? fmaxf(acc, 0.f) : acc);
}

template <bool RELU>
__global__ void k_agg512(const __nv_bfloat16* __restrict__ xw, const float* __restrict__ bias,
                         __nv_bfloat16* __restrict__ out) {
    int v = blockIdx.x;
    int f2 = threadIdx.x * 2;
    float dv = g_dinv[v];
    float sw = dv * dv;
    int rs = g_offsets[v];
    int re = rs + g_counts[v];
    float2 self = __bfloat1622float2(*(const __nv_bfloat162*)(xw + (size_t)v * 512 + f2));
    float a0 = sw * self.x, a1 = sw * self.y;
    for (int i = rs; i < re; i++) {
        float w = g_wts[i];
        float2 m = __bfloat1622float2(*(const __nv_bfloat162*)(xw + (size_t)g_srcs[i] * 512 + f2));
        a0 += w * m.x;
        a1 += w * m.y;
    }
    a0 += bias[f2]; a1 += bias[f2 + 1];
    if (RELU) { a0 = fmaxf(a0, 0.f); a1 = fmaxf(a1, 0.f); }
    __nv_bfloat162 h;
    h.x = __float2bfloat16_rn(a0);
    h.y = __float2bfloat16_rn(a1);
    *(__nv_bfloat162*)(out + (size_t)v * 512 + f2) = h;
}

// ---------------- cp.async / ldmatrix helpers ----------------
__device__ __forceinline__ void cp16(uint32_t smem, const void* gmem, int srcBytes) {
    asm volatile("cp.async.cg.shared.global [%0], [%1], 16, %2;"
                 :: "r"(smem), "l"(gmem), "r"(srcBytes));
}
__device__ __forceinline__ void cp_commit() { asm volatile("cp.async.commit_group;"); }
template <int N>
__device__ __forceinline__ void cp_wait() { asm volatile("cp.async.wait_group %0;" :: "n"(N)); }

__device__ __forceinline__ void ldsm4(uint32_t& r0, uint32_t& r1, uint32_t& r2, uint32_t& r3,
                                      uint32_t addr) {
    asm volatile("ldmatrix.sync.aligned.m8n8.x4.shared.b16 {%0,%1,%2,%3}, [%4];"
                 : "=r"(r0), "=r"(r1), "=r"(r2), "=r"(r3) : "r"(addr));
}

#define SSTR 40  // smem row stride in bf16 elems (80B = 5*16B, ldmatrix-aligned)
#define STGB (128 * SSTR * 2)  // bytes per stage per array

// warp-tile mma via ldmatrix: 64x32 per warp from one 128x32 stage
__device__ __forceinline__ void mma_tile(uint32_t sAs, uint32_t sBs,
                                         int wm, int wn, int lane,
                                         float acc[4][4][4]) {
    // ldmatrix lane-address offsets (in elements)
    const int aRow = (lane & 7) + ((lane >> 3) & 1) * 8;
    const int aCol = (lane >> 4) * 8;
    const int bRow = (lane & 7) + (lane >> 4) * 8;
    const int bCol = ((lane >> 3) & 1) * 8;
#pragma unroll
    for (int kk = 0; kk < 32; kk += 16) {
        uint32_t af[4][4], bf[4][2];
#pragma unroll
        for (int mi = 0; mi < 4; mi++) {
            uint32_t a = sAs + ((wm + mi * 16 + aRow) * SSTR + kk + aCol) * 2;
            ldsm4(af[mi][0], af[mi][1], af[mi][2], af[mi][3], a);
        }
#pragma unroll
        for (int p = 0; p < 2; p++) {
            uint32_t b = sBs + ((wn + p * 16 + bRow) * SSTR + kk + bCol) * 2;
            ldsm4(bf[2 * p][0], bf[2 * p][1], bf[2 * p + 1][0], bf[2 * p + 1][1], b);
        }
#pragma unroll
        for (int mi = 0; mi < 4; mi++)
#pragma unroll
            for (int ni = 0; ni < 4; ni++) {
                asm volatile(
                    "mma.sync.aligned.m16n8k16.row.col.f32.bf16.bf16.f32 "
                    "{%0,%1,%2,%3}, {%4,%5,%6,%7}, {%8,%9}, {%0,%1,%2,%3};"
                    : "+f"(acc[mi][ni][0]), "+f"(acc[mi][ni][1]),
                      "+f"(acc[mi][ni][2]), "+f"(acc[mi][ni][3])
                    : "r"(af[mi][0]), "r"(af[mi][1]), "r"(af[mi][2]), "r"(af[mi][3]),
                      "r"(bf[ni][0]), "r"(bf[ni][1]));
            }
    }
}

// 3-stage K-loop: one __syncthreads per stage.
// cpA/cpB issue the global->shared copies for K-offset k0 into stage slot.
#define GEMM_MAINLOOP(nK, ISSUE)                                             \
    ISSUE(0, 0); cp_commit();                                                \
    ISSUE(32, 1); cp_commit();                                               \
    for (int i = 0; i < (nK); i++) {                                         \
        cp_wait<1>();                                                        \
        __syncthreads();                                                     \
        if (i + 2 < (nK)) { ISSUE((i + 2) * 32, (i + 2) % 3); }              \
        cp_commit();                                                         \
        mma_tile(sAbase + ((i % 3) * STGB), sBbase + ((i % 3) * STGB),       \
                 wm, wn, lane, acc);                                         \
    }

// ---------------- bf16 NT GEMM, 3-stage cp.async pipeline --------------
template <bool RELU, bool BIAS>
__global__ void bgemm(int M, int N, int K,
                      const __nv_bfloat16* __restrict__ A,
                      const __nv_bfloat16* __restrict__ B,
                      __nv_bfloat16* __restrict__ C,
                      const float* __restrict__ bias) {
    __shared__ __align__(16) __nv_bfloat16 As[3][128 * SSTR];
    __shared__ __align__(16) __nv_bfloat16 Bs[3][128 * SSTR];
    const int tid = threadIdx.x;
    const int lane = tid & 31, warp = tid >> 5;
    const int wm = (warp & 1) * 64, wn = (warp >> 1) * 32;
    const int g = lane >> 2, tg = lane & 3;
    const int brow = blockIdx.y * 128, bcol = blockIdx.x * 128;

    float acc[4][4][4];
#pragma unroll
    for (int a = 0; a < 4; a++)
#pragma unroll
        for (int b = 0; b < 4; b++)
#pragma unroll
            for (int c = 0; c < 4; c++) acc[a][b][c] = 0.f;

    const int lrow = tid >> 1;
    const int lk = (tid & 1) * 16;
    int arow = brow + lrow;
    bool aval = arow < M;
    int aSrc = aval ? 16 : 0;
    const __nv_bfloat16* Ap = A + (long)(aval ? arow : 0) * K + lk;
    const __nv_bfloat16* Bp = B + (long)(bcol + lrow) * K + lk;

    uint32_t sAbase = (uint32_t)__cvta_generic_to_shared(&As[0][0]);
    uint32_t sBbase = (uint32_t)__cvta_generic_to_shared(&Bs[0][0]);
    uint32_t sA = sAbase + (lrow * SSTR + lk) * 2;
    uint32_t sB = sBbase + (lrow * SSTR + lk) * 2;

    const int nK = K / 32;
#define ISSUE_G(k0, slot)                                                    \
    cp16(sA + (slot) * STGB, Ap + (k0), aSrc);                               \
    cp16(sA + (slot) * STGB + 16, Ap + (k0) + 8, aSrc);                      \
    cp16(sB + (slot) * STGB, Bp + (k0), 16);                                 \
    cp16(sB + (slot) * STGB + 16, Bp + (k0) + 8, 16);
    GEMM_MAINLOOP(nK, ISSUE_G)
#undef ISSUE_G

#pragma unroll
    for (int mi = 0; mi < 4; mi++) {
#pragma unroll
        for (int half = 0; half < 2; half++) {
            int r = brow + wm + mi * 16 + g + half * 8;
            if (r >= M) continue;
#pragma unroll
            for (int ni = 0; ni < 4; ni++) {
                int c = bcol + wn + ni * 8 + tg * 2;
                float v0 = acc[mi][ni][half * 2 + 0];
                float v1 = acc[mi][ni][half * 2 + 1];
                if (BIAS) { v0 += bias[c]; v1 += bias[c + 1]; }
                if (RELU) { v0 = fmaxf(v0, 0.f); v1 = fmaxf(v1, 0.f); }
                __nv_bfloat162 h;
                h.x = __float2bfloat16_rn(v0);
                h.y = __float2bfloat16_rn(v1);
                *(__nv_bfloat162*)(C + (size_t)r * N + c) = h;
            }
        }
    }
}

// ------- fused logits GEMM + online row LSE + diag extraction -------------
// grid = (NCHUNK=8, NB/128=32). Each block: 128 rows x 512 cols (4 tiles of 128).
__global__ void k_logits_lse(const __nv_bfloat16* __restrict__ A,   // gcn [NN][DD]
                             const __nv_bfloat16* __restrict__ B,   // img [NB][DD]
                             const int* __restrict__ label) {
    __shared__ __align__(16) __nv_bfloat16 As[3][128 * SSTR];
    __shared__ __align__(16) __nv_bfloat16 Bs[3][128 * SSTR];
    __shared__ float red_m[4][128];
    __shared__ float red_s[4][128];
    __shared__ float run_m[128];
    __shared__ float run_s[128];

    const int tid = threadIdx.x;
    const int lane = tid & 31, warp = tid >> 5;
    const int wm = (warp & 1) * 64, wn = (warp >> 1) * 32;
    const int wnIdx = warp >> 1;
    const int g = lane >> 2, tg = lane & 3;
    const int brow = blockIdx.y * 128;
    const int chunk = blockIdx.x;

    const int lrow = tid >> 1;
    const int lk = (tid & 1) * 16;
    const __nv_bfloat16* Ap = A + (long)label[brow + lrow] * DD + lk;

    uint32_t sAbase = (uint32_t)__cvta_generic_to_shared(&As[0][0]);
    uint32_t sBbase = (uint32_t)__cvta_generic_to_shared(&Bs[0][0]);
    uint32_t sA = sAbase + (lrow * SSTR + lk) * 2;
    uint32_t sB = sBbase + (lrow * SSTR + lk) * 2;

    if (tid < 128) { run_m[tid] = -3.0e38f; run_s[tid] = 0.f; }

    for (int nt = 0; nt < 4; nt++) {
        const int bcol = chunk * 512 + nt * 128;
        const __nv_bfloat16* Bp = B + (long)(bcol + lrow) * DD + lk;

        float acc[4][4][4];
#pragma unroll
        for (int a = 0; a < 4; a++)
#pragma unroll
            for (int b = 0; b < 4; b++)
#pragma unroll
                for (int c = 0; c < 4; c++) acc[a][b][c] = 0.f;

        const int nK = DD / 32;
#define ISSUE_L(k0, slot)                                                    \
    cp16(sA + (slot) * STGB, Ap + (k0), 16);                                 \
    cp16(sA + (slot) * STGB + 16, Ap + (k0) + 8, 16);                        \
    cp16(sB + (slot) * STGB, Bp + (k0), 16);                                 \
    cp16(sB + (slot) * STGB + 16, Bp + (k0) + 8, 16);
        GEMM_MAINLOOP(nK, ISSUE_L)
#undef ISSUE_L

        __syncthreads();  // protect smem reuse + red arrays

        // ---- epilogue: online LSE over this 128x128 tile ----
#pragma unroll
        for (int mi = 0; mi < 4; mi++) {
#pragma unroll
            for (int half = 0; half < 2; half++) {
                int row = wm + mi * 16 + g + half * 8;
                float v = -3.0e38f;
#pragma unroll
                for (int ni = 0; ni < 4; ni++)
                    v = fmaxf(v, fmaxf(acc[mi][ni][half * 2], acc[mi][ni][half * 2 + 1]));
                v = fmaxf(v, __shfl_xor_sync(0xffffffffu, v, 1));
                v = fmaxf(v, __shfl_xor_sync(0xffffffffu, v, 2));
                if (tg == 0) red_m[wnIdx][row] = v;
            }
        }
        __syncthreads();
        if (tid < 128) {
            float tm = fmaxf(fmaxf(red_m[0][tid], red_m[1][tid]),
                             fmaxf(red_m[2][tid], red_m[3][tid]));
            float om = run_m[tid];
            float nm = fmaxf(om, tm);
            run_s[tid] *= __expf(om - nm);
            run_m[tid] = nm;
        }
        __syncthreads();
#pragma unroll
        for (int mi = 0; mi < 4; mi++) {
#pragma unroll
            for (int half = 0; half < 2; half++) {
                int row = wm + mi * 16 + g + half * 8;
                float nm = run_m[row];
                float ps = 0.f;
#pragma unroll
                for (int ni = 0; ni < 4; ni++) {
#pragma unroll
                    for (int j = 0; j < 2; j++) {
                        float v = acc[mi][ni][half * 2 + j];
                        ps += __expf(v - nm);
                        int gc = bcol + wn + ni * 8 + tg * 2 + j;
                        if (gc == brow + row) g_diag[brow + row] = v;
                    }
                }
                ps += __shfl_xor_sync(0xffffffffu, ps, 1);
                ps += __shfl_xor_sync(0xffffffffu, ps, 2);
                if (tg == 0) red_s[wnIdx][row] = ps;
            }
        }
        __syncthreads();
        if (tid < 128)
            run_s[tid] += red_s[0][tid] + red_s[1][tid] + red_s[2][tid] + red_s[3][tid];
        __syncthreads();
    }

    if (tid < 128) {
        g_pm[chunk * NB + brow + tid] = run_m[tid];
        g_ps[chunk * NB + brow + tid] = run_s[tid];
    }
}

// ---------------- merge partials + final scalar (fused, 1 block) -----------
__global__ void k_finish(const int* __restrict__ label, float* __restrict__ out) {
    __shared__ float sh[256];
    float local = 0.f;
    for (int i = threadIdx.x; i < NB; i += 256) {
        float m = -3.0e38f;
#pragma unroll
        for (int c = 0; c < NCHUNK; c++) m = fmaxf(m, g_pm[c * NB + i]);
        float s = 0.f;
#pragma unroll
        for (int c = 0; c < NCHUNK; c++) s += g_ps[c * NB + i] * __expf(g_pm[c * NB + i] - m);
        float lse = m + logf(s);
        local += -(float)label[i] * (g_diag[i] - lse);
    }
    sh[threadIdx.x] = local;
    __syncthreads();
    for (int off = 128; off > 0; off >>= 1) {
        if (threadIdx.x < off) sh[threadIdx.x] += sh[threadIdx.x + off];
        __syncthreads();
    }
    if (threadIdx.x == 0) out[0] = sh[0] / (float)NB + 1.0f;  // + triplet (==1 exactly)
}

// ---------------- launch ----------------
extern "C" void kernel_launch(void* const* d_in, const int* in_sizes, int n_in,
                              void* d_out, int out_size) {
    const float* image  = (const float*)d_in[0];
    const float* xnodes = (const float*)d_in[1];
    const int*   ei     = (const int*)d_in[2];
    const int*   label  = (const int*)d_in[3];
    const float* W_img1 = (const float*)d_in[4];
    const float* b_img1 = (const float*)d_in[5];
    const float* W_img2 = (const float*)d_in[6];
    const float* b_img2 = (const float*)d_in[7];
    const float* W_g1   = (const float*)d_in[8];
    const float* b_g1   = (const float*)d_in[9];
    const float* W_g2   = (const float*)d_in[10];
    const float* b_g2   = (const float*)d_in[11];

    __nv_bfloat16 *p_xa, *p_ia, *p_wg1t, *p_wg2t, *p_wi1t, *p_wi2t;
    __nv_bfloat16 *p_xw1, *p_h, *p_xw2, *p_gcn, *p_t1, *p_img;
    cudaGetSymbolAddress((void**)&p_xa, g_xa);
    cudaGetSymbolAddress((void**)&p_ia, g_ia);
    cudaGetSymbolAddress((void**)&p_wg1t, g_wg1t);
    cudaGetSymbolAddress((void**)&p_wg2t, g_wg2t);
    cudaGetSymbolAddress((void**)&p_wi1t, g_wi1t);
    cudaGetSymbolAddress((void**)&p_wi2t, g_wi2t);
    cudaGetSymbolAddress((void**)&p_xw1, g_xw1);
    cudaGetSymbolAddress((void**)&p_h, g_h);
    cudaGetSymbolAddress((void**)&p_xw2, g_xw2);
    cudaGetSymbolAddress((void**)&p_gcn, g_gcn);
    cudaGetSymbolAddress((void**)&p_t1, g_t1);
    cudaGetSymbolAddress((void**)&p_img, g_img);

    // graph preprocessing -> CSR + symmetric norm weights
    k_init<<<(NN + 255) / 256, 256>>>();
    k_count<<<(NE + 255) / 256, 256>>>(ei);
    k_scan<<<1, 1024>>>();
    k_fill<<<(NE + 255) / 256, 256>>>(ei);

    // dtype conversions
    k_conv<<<(NN * DD / 4 + 255) / 256, 256>>>(xnodes, p_xa, NN * DD);
    k_conv<<<(NB * DD / 4 + 255) / 256, 256>>>(image, p_ia, NB * DD);
    k_convT<<<dim3(HH / 32, DD / 32), dim3(32, 32)>>>(W_g1, p_wg1t, DD, HH);
    k_convT<<<dim3(DD / 32, HH / 32), dim3(32, 32)>>>(W_g2, p_wg2t, HH, DD);
    k_convT<<<dim3(HH / 32, DD / 32), dim3(32, 32)>>>(W_img1, p_wi1t, DD, HH);
    k_convT<<<dim3(DD / 32, HH / 32), dim3(32, 32)>>>(W_img2, p_wi2t, HH, DD);

    // GCN layer 1
    {
        dim3 grid(HH / 128, (NN + 127) / 128);
        bgemm<false, false><<<grid, 256>>>(NN, HH, DD, p_xa, p_wg1t, p_xw1, nullptr);
    }
    k_agg256<true><<<NN, 256>>>(p_xw1, b_g1, p_h);

    // GCN layer 2
    {
        dim3 grid(DD / 128, (NN + 127) / 128);
        bgemm<false, false><<<grid, 256>>>(NN, DD, HH, p_h, p_wg2t, p_xw2, nullptr);
    }
    k_agg512<false><<<NN, 256>>>(p_xw2, b_g2, p_gcn);

    // image MLP
    {
        dim3 grid(HH / 128, NB / 128);
        bgemm<true, true><<<grid, 256>>>(NB, HH, DD, p_ia, p_wi1t, p_t1, b_img1);
    }
    {
        dim3 grid(DD / 128, NB / 128);
        bgemm<true, true><<<grid, 256>>>(NB, DD, HH, p_t1, p_wi2t, p_img, b_img2);
    }

    // fused logits + row-wise LSE partials + diag
    {
        dim3 grid(NCHUNK, NB / 128);
        k_logits_lse<<<grid, 256>>>(p_gcn, p_img, label);
    }
    k_finish<<<1, 256>>>(label, (float*)d_out);
}